// round 7
// baseline (speedup 1.0000x reference)
#include <cuda_runtime.h>
#include <math.h>
#include <stdint.h>

#define NPRED_TOTAL 259584      // 32 * 8112
#define NP0         8112        // predictions in batch 0 (3*52*52)
#define HW_         2704        // 52*52
#define ATTRS       85
#define OUT_ELEMS   22064640    // 32*8112*85
#define MAXDET      100
#define NCLS        80
#define CLS_CAP     1024        // per-class cand cap (expected ~46; 146 sigma margin)
#define KEPT_MAX    8192        // >= NCLS * MAXDET

// ---- device scratch ----
__device__ float4   g_obox[NP0];
__device__ float4   g_corners[NP0];
__device__ float    g_conf[NP0];
__device__ float    g_clsconf[NP0];
__device__ float    g_clspred[NP0];
__device__ uint64_t g_cls_list[NCLS * CLS_CAP];  // per-class candidate keys
__device__ int      g_cls_cnt[NCLS];             // zero-init; reset by class_nms
__device__ uint64_t g_kept[KEPT_MAX];            // kept keys (all classes)
__device__ int      g_kcount;                    // zero-init; reset by merge

// key = score_inv(32) << 20 | idx(13) << 7 | cls(7)
// ascending key == score desc, then flat idx asc (matches jnp.argmax ties)

__device__ __forceinline__ float sigf(float x) { return 1.0f / (1.0f + expf(-x)); }

// ---------------------------------------------------------------------------
// Decode: 64 preds per 256-thread block, quarter-split over attrs (identical
// math to the R5 kernel that passed). Candidates scatter directly into
// per-class lists (order within a list is irrelevant: value-sorted later).
// ---------------------------------------------------------------------------
__global__ __launch_bounds__(256) void decode_kernel(
    const float* __restrict__ in,
    const float* __restrict__ anchors,
    float* __restrict__ out)
{
    __shared__ float sm[64 * ATTRS];
    const int tx = threadIdx.x;
    const int q  = tx >> 6;
    const int lp = tx & 63;
    const int n  = blockIdx.x * 64 + lp;
    const int b  = n / NP0;
    const int r  = n - b * NP0;
    const int a  = r / HW_;
    const int hw = r - a * HW_;
    const int gy = hw / 52;
    const int gx = hw - gy * 52;

    const float* p = in + ((long)(b * 255 + a * 85)) * HW_ + hw;
    float* row = sm + lp * ATTRS;

    float t[22];
    #pragma unroll
    for (int k = 0; k < 22; k++) {
        int e = q + 4 * k;
        if (e < ATTRS) t[k] = p[(long)e * HW_];
    }

    if (q == 0) {
        row[0] = (sigf(t[0]) + (float)gx) / 52.0f;
        row[4] = sigf(t[1]);
        #pragma unroll
        for (int k = 2; k < 22; k++) row[4 * k] = sigf(t[k]);
    } else if (q == 1) {
        row[1] = (sigf(t[0]) + (float)gy) / 52.0f;
        #pragma unroll
        for (int k = 1; k < 21; k++) row[1 + 4 * k] = sigf(t[k]);
    } else if (q == 2) {
        float aw = anchors[(6 + a) * 2 + 0] * 0.125f;
        row[2] = (expf(t[0]) * aw) / 52.0f;
        #pragma unroll
        for (int k = 1; k < 21; k++) row[2 + 4 * k] = sigf(t[k]);
    } else {
        float ah = anchors[(6 + a) * 2 + 1] * 0.125f;
        row[3] = (expf(t[0]) * ah) / 52.0f;
        #pragma unroll
        for (int k = 1; k < 21; k++) row[3 + 4 * k] = sigf(t[k]);
    }
    __syncthreads();

    {
        const float4* sm4 = (const float4*)sm;
        float4* ob4 = (float4*)(out + (long)blockIdx.x * (64 * ATTRS));
        #pragma unroll 6
        for (int i = tx; i < (64 * ATTRS) / 4; i += 256) ob4[i] = sm4[i];
    }

    // batch-0 candidate extraction -> per-class scatter
    if (tx < 64 && n < NP0) {
        float conf = row[4];
        float cc = row[5]; int cp = 0;
        #pragma unroll 16
        for (int c = 1; c < NCLS; c++) {
            float v = row[5 + c];
            if (v > cc) { cc = v; cp = c; }   // strict > : lowest idx on ties
        }
        float score = conf * cc;
        if (score >= 0.5f) {
            float bx = row[0], by = row[1], bw = row[2], bh = row[3];
            float hx = bw * 0.5f, hy = bh * 0.5f;
            float x1 = bx - hx, y1 = by - hy, x2 = bx + hx, y2 = by + hy;
            float off = (float)cp * 4096.0f;
            g_corners[n] = make_float4(x1, y1, x2, y2);
            g_obox[n]    = make_float4(x1 + off, y1 + off, x2 + off, y2 + off);
            g_conf[n]    = conf;
            g_clsconf[n] = cc;
            g_clspred[n] = (float)cp;
            uint64_t key = ((uint64_t)(__float_as_uint(score) ^ 0xFFFFFFFFu) << 20)
                         | ((uint64_t)(unsigned)n << 7) | (unsigned)cp;
            int pos = atomicAdd(&g_cls_cnt[cp], 1);
            if (pos < CLS_CAP) g_cls_list[cp * CLS_CAP + pos] = key;
        }
    }
}

// ---------------------------------------------------------------------------
// Per-class NMS: one 256-thread block per class, fully smem-resident.
//  1) load own candidate keys  2) local rank sort (exact permutation)
//  3) gather offset boxes      4) warp-0 greedy sweep (kept cap 100: exact)
//  5) append kept keys to global list; reset class counter for next replay.
// ---------------------------------------------------------------------------
__global__ __launch_bounds__(256) void class_nms_kernel()
{
    __shared__ uint64_t s_key[CLS_CAP];    // 8KB
    __shared__ uint64_t s_sort[CLS_CAP];   // 8KB
    __shared__ float4   s_box[CLS_CAP];    // 16KB
    __shared__ float4   s_k[MAXDET];
    __shared__ float    s_ka[MAXDET];
    __shared__ int      s_kidx[MAXDET];
    __shared__ int      s_nk, s_gbase;

    const int tid = threadIdx.x;
    const int c   = blockIdx.x;
    int nc = g_cls_cnt[c]; if (nc > CLS_CAP) nc = CLS_CAP;

    for (int i = tid; i < nc; i += 256) s_key[i] = g_cls_list[c * CLS_CAP + i];
    __syncthreads();

    // local rank sort: ascending key = score desc, idx asc
    for (int i = tid; i < nc; i += 256) {
        uint64_t my = s_key[i];
        int rk = 0;
        for (int j = 0; j < nc; j++) rk += (s_key[j] < my) ? 1 : 0;
        s_sort[rk] = my;
    }
    __syncthreads();

    // gather boxes in sorted order
    for (int i = tid; i < nc; i += 256) {
        int orig = (int)((s_sort[i] >> 7) & 0x1FFFu);
        s_box[i] = g_obox[orig];
    }
    __syncthreads();

    // warp-0 greedy sweep, lane-parallel over kept boxes
    if (tid < 32) {
        const int lane = tid;
        int nk = 0;
        for (int i = 0; i < nc && nk < MAXDET; i++) {
            float4 B = s_box[i];
            float aC = (B.z - B.x) * (B.w - B.y);
            bool sup = false;
            #pragma unroll
            for (int t = 0; t < 4; t++) {
                int idx = lane + (t << 5);
                if (idx < nk) {
                    float4 K = s_k[idx];
                    float ltx = fmaxf(K.x, B.x), lty = fmaxf(K.y, B.y);
                    float rbx = fminf(K.z, B.z), rby = fminf(K.w, B.w);
                    float iw = fmaxf(rbx - ltx, 0.0f), ih = fmaxf(rby - lty, 0.0f);
                    float inter = iw * ih;
                    float den = s_ka[idx] + aC - inter + 1e-9f;  // a1 + a2 - inter + eps
                    if (inter / den > 0.4f) sup = true;
                }
            }
            if (__ballot_sync(0xffffffffu, sup) == 0u) {
                if (lane == 0) { s_k[nk] = B; s_ka[nk] = aC; s_kidx[nk] = i; }
                nk++;
                __syncwarp();
            }
        }
        if (lane == 0) s_nk = nk;
    }
    __syncthreads();

    const int nk = s_nk;
    if (tid == 0) s_gbase = (nk > 0) ? atomicAdd(&g_kcount, nk) : 0;
    __syncthreads();
    for (int t = tid; t < nk; t += 256) {
        int gp = s_gbase + t;
        if (gp < KEPT_MAX) g_kept[gp] = s_sort[s_kidx[t]];
    }

    if (tid == 0) g_cls_cnt[c] = 0;   // reset for next graph replay
}

// ---------------------------------------------------------------------------
// Merge: rank-select the 100 smallest kept keys (= global score-desc order,
// exact since cross-class IoU == 0), emit det rows, reset kept counter.
// ---------------------------------------------------------------------------
__global__ __launch_bounds__(256) void merge_kernel(float* __restrict__ out)
{
    extern __shared__ uint64_t skept[];    // KEPT_MAX * 8B = 64KB dynamic
    __shared__ int s_ord[MAXDET];

    const int tid = threadIdx.x;
    int K = g_kcount; if (K > KEPT_MAX) K = KEPT_MAX;

    for (int i = tid; i < K; i += 256) skept[i] = g_kept[i];
    __syncthreads();

    for (int i = tid; i < K; i += 256) {
        uint64_t my = skept[i];
        int rk = 0;
        for (int j = 0; j < K; j++) rk += (skept[j] < my) ? 1 : 0;
        if (rk < MAXDET) s_ord[rk] = (int)((my >> 7) & 0x1FFFu);
    }
    __syncthreads();

    int np = (K < MAXDET) ? K : MAXDET;
    if (tid < MAXDET) {
        float* d = out + (long)OUT_ELEMS + tid * 7;
        if (tid < np) {
            int orig = s_ord[tid];
            float4 c4 = g_corners[orig];
            d[0] = c4.y * 416.0f;
            d[1] = c4.x * 416.0f;
            d[2] = c4.w * 416.0f;
            d[3] = c4.z * 416.0f;
            d[4] = g_conf[orig];
            d[5] = g_clsconf[orig];
            d[6] = g_clspred[orig];
        } else {
            #pragma unroll
            for (int e = 0; e < 7; e++) d[e] = 0.0f;
        }
    }

    if (tid == 0) g_kcount = 0;   // reset for next graph replay
}

extern "C" void kernel_launch(void* const* d_in, const int* in_sizes, int n_in,
                              void* d_out, int out_size)
{
    const float* in      = (const float*)d_in[0];
    const float* anchors = (const float*)d_in[1];
    float* out = (float*)d_out;

    static int attr_set = 0;
    if (!attr_set) {
        cudaFuncSetAttribute(merge_kernel, cudaFuncAttributeMaxDynamicSharedMemorySize,
                             KEPT_MAX * (int)sizeof(uint64_t));
        attr_set = 1;
    }

    decode_kernel<<<NPRED_TOTAL / 64, 256>>>(in, anchors, out);
    class_nms_kernel<<<NCLS, 256>>>();
    merge_kernel<<<1, 256, KEPT_MAX * sizeof(uint64_t)>>>(out);
}

// round 8
// speedup vs baseline: 5.4213x; 5.4213x over previous
#include <cuda_runtime.h>
#include <math.h>
#include <stdint.h>

#define NPRED_TOTAL 259584      // 32 * 8112
#define NP0         8112        // predictions in batch 0 (3*52*52)
#define HW_         2704        // 52*52
#define ATTRS       85
#define OUT_ELEMS   22064640    // 32*8112*85
#define MAXDET      100
#define NCLS        80
#define CLS_CAP     1024        // per-class cand cap (expected ~46)
#define KEPT_MAX    8192        // >= NCLS * MAXDET
#define NBUCK       8192        // top-13 bits of score_inv
#define POOL_CAP    1536

// ---- device scratch ----
__device__ float4   g_obox[NP0];
__device__ float4   g_corners[NP0];
__device__ float    g_conf[NP0];
__device__ float    g_clsconf[NP0];
__device__ float    g_clspred[NP0];
__device__ uint64_t g_cls_list[NCLS * CLS_CAP];  // per-class candidate keys
__device__ int      g_cls_cnt[NCLS];             // zero-init; reset by class_nms
__device__ uint64_t g_kept[KEPT_MAX];            // kept keys (all classes)
__device__ int      g_kcount;                    // zero-init; reset by merge

// key (52 bits) = score_inv(32) << 20 | idx(13) << 7 | cls(7)
// ascending key == score desc, then flat idx asc (matches jnp.argmax ties)

__device__ __forceinline__ float sigf(float x) { return 1.0f / (1.0f + expf(-x)); }

// ---------------------------------------------------------------------------
// Decode (unchanged from R7: 31.7us, 50.8% DRAM SOL)
// ---------------------------------------------------------------------------
__global__ __launch_bounds__(256) void decode_kernel(
    const float* __restrict__ in,
    const float* __restrict__ anchors,
    float* __restrict__ out)
{
    __shared__ float sm[64 * ATTRS];
    const int tx = threadIdx.x;
    const int q  = tx >> 6;
    const int lp = tx & 63;
    const int n  = blockIdx.x * 64 + lp;
    const int b  = n / NP0;
    const int r  = n - b * NP0;
    const int a  = r / HW_;
    const int hw = r - a * HW_;
    const int gy = hw / 52;
    const int gx = hw - gy * 52;

    const float* p = in + ((long)(b * 255 + a * 85)) * HW_ + hw;
    float* row = sm + lp * ATTRS;

    float t[22];
    #pragma unroll
    for (int k = 0; k < 22; k++) {
        int e = q + 4 * k;
        if (e < ATTRS) t[k] = p[(long)e * HW_];
    }

    if (q == 0) {
        row[0] = (sigf(t[0]) + (float)gx) / 52.0f;
        row[4] = sigf(t[1]);
        #pragma unroll
        for (int k = 2; k < 22; k++) row[4 * k] = sigf(t[k]);
    } else if (q == 1) {
        row[1] = (sigf(t[0]) + (float)gy) / 52.0f;
        #pragma unroll
        for (int k = 1; k < 21; k++) row[1 + 4 * k] = sigf(t[k]);
    } else if (q == 2) {
        float aw = anchors[(6 + a) * 2 + 0] * 0.125f;
        row[2] = (expf(t[0]) * aw) / 52.0f;
        #pragma unroll
        for (int k = 1; k < 21; k++) row[2 + 4 * k] = sigf(t[k]);
    } else {
        float ah = anchors[(6 + a) * 2 + 1] * 0.125f;
        row[3] = (expf(t[0]) * ah) / 52.0f;
        #pragma unroll
        for (int k = 1; k < 21; k++) row[3 + 4 * k] = sigf(t[k]);
    }
    __syncthreads();

    {
        const float4* sm4 = (const float4*)sm;
        float4* ob4 = (float4*)(out + (long)blockIdx.x * (64 * ATTRS));
        #pragma unroll 6
        for (int i = tx; i < (64 * ATTRS) / 4; i += 256) ob4[i] = sm4[i];
    }

    if (tx < 64 && n < NP0) {
        float conf = row[4];
        float cc = row[5]; int cp = 0;
        #pragma unroll 16
        for (int c = 1; c < NCLS; c++) {
            float v = row[5 + c];
            if (v > cc) { cc = v; cp = c; }   // strict > : lowest idx on ties
        }
        float score = conf * cc;
        if (score >= 0.5f) {
            float bx = row[0], by = row[1], bw = row[2], bh = row[3];
            float hx = bw * 0.5f, hy = bh * 0.5f;
            float x1 = bx - hx, y1 = by - hy, x2 = bx + hx, y2 = by + hy;
            float off = (float)cp * 4096.0f;
            g_corners[n] = make_float4(x1, y1, x2, y2);
            g_obox[n]    = make_float4(x1 + off, y1 + off, x2 + off, y2 + off);
            g_conf[n]    = conf;
            g_clsconf[n] = cc;
            g_clspred[n] = (float)cp;
            uint64_t key = ((uint64_t)(__float_as_uint(score) ^ 0xFFFFFFFFu) << 20)
                         | ((uint64_t)(unsigned)n << 7) | (unsigned)cp;
            int pos = atomicAdd(&g_cls_cnt[cp], 1);
            if (pos < CLS_CAP) g_cls_list[cp * CLS_CAP + pos] = key;
        }
    }
}

// ---------------------------------------------------------------------------
// Per-class NMS (unchanged from R7): smem-resident sort + warp greedy sweep.
// ---------------------------------------------------------------------------
__global__ __launch_bounds__(256) void class_nms_kernel()
{
    __shared__ uint64_t s_key[CLS_CAP];
    __shared__ uint64_t s_sort[CLS_CAP];
    __shared__ float4   s_box[CLS_CAP];
    __shared__ float4   s_k[MAXDET];
    __shared__ float    s_ka[MAXDET];
    __shared__ int      s_kidx[MAXDET];
    __shared__ int      s_nk, s_gbase;

    const int tid = threadIdx.x;
    const int c   = blockIdx.x;
    int nc = g_cls_cnt[c]; if (nc > CLS_CAP) nc = CLS_CAP;

    for (int i = tid; i < nc; i += 256) s_key[i] = g_cls_list[c * CLS_CAP + i];
    __syncthreads();

    for (int i = tid; i < nc; i += 256) {
        uint64_t my = s_key[i];
        int rk = 0;
        for (int j = 0; j < nc; j++) rk += (s_key[j] < my) ? 1 : 0;
        s_sort[rk] = my;
    }
    __syncthreads();

    for (int i = tid; i < nc; i += 256) {
        int orig = (int)((s_sort[i] >> 7) & 0x1FFFu);
        s_box[i] = g_obox[orig];
    }
    __syncthreads();

    if (tid < 32) {
        const int lane = tid;
        int nk = 0;
        for (int i = 0; i < nc && nk < MAXDET; i++) {
            float4 B = s_box[i];
            float aC = (B.z - B.x) * (B.w - B.y);
            bool sup = false;
            #pragma unroll
            for (int t = 0; t < 4; t++) {
                int idx = lane + (t << 5);
                if (idx < nk) {
                    float4 K = s_k[idx];
                    float ltx = fmaxf(K.x, B.x), lty = fmaxf(K.y, B.y);
                    float rbx = fminf(K.z, B.z), rby = fminf(K.w, B.w);
                    float iw = fmaxf(rbx - ltx, 0.0f), ih = fmaxf(rby - lty, 0.0f);
                    float inter = iw * ih;
                    float den = s_ka[idx] + aC - inter + 1e-9f;  // a1 + a2 - inter + eps
                    if (inter / den > 0.4f) sup = true;
                }
            }
            if (__ballot_sync(0xffffffffu, sup) == 0u) {
                if (lane == 0) { s_k[nk] = B; s_ka[nk] = aC; s_kidx[nk] = i; }
                nk++;
                __syncwarp();
            }
        }
        if (lane == 0) s_nk = nk;
    }
    __syncthreads();

    const int nk = s_nk;
    if (tid == 0) s_gbase = (nk > 0) ? atomicAdd(&g_kcount, nk) : 0;
    __syncthreads();
    for (int t = tid; t < nk; t += 256) {
        int gp = s_gbase + t;
        if (gp < KEPT_MAX) g_kept[gp] = s_sort[s_kidx[t]];
    }

    if (tid == 0) g_cls_cnt[c] = 0;   // reset for next graph replay
}

// ---------------------------------------------------------------------------
// Merge v2: O(K) histogram top-100 select (replaces the K^2 rank sort that
// cost ~350us at K~3500).
//  1) 8192-bucket histogram on top-13 bits of score_inv (key>>39)
//  2) warp 0 finds bucket B* containing rank np-1 (chunked scan)
//  3) compact keys with bucket <= B* into pool (~320 expected)
//  4) exact rank-sort of pool, emit ranks < np
// ---------------------------------------------------------------------------
__global__ __launch_bounds__(1024) void merge_kernel(float* __restrict__ out)
{
    __shared__ int      s_hist[NBUCK];     // 32KB
    __shared__ uint64_t s_pool[POOL_CAP];  // 12KB
    __shared__ int      s_ord[MAXDET];
    __shared__ int      s_bstar, s_pcnt;

    const int tid = threadIdx.x;
    int K = g_kcount; if (K > KEPT_MAX) K = KEPT_MAX;
    const int np = (K < MAXDET) ? K : MAXDET;

    for (int i = tid; i < NBUCK; i += 1024) s_hist[i] = 0;
    if (tid == 0) { s_pcnt = 0; s_bstar = -1; }
    __syncthreads();

    for (int i = tid; i < K; i += 1024)
        atomicAdd(&s_hist[(int)(g_kept[i] >> 39)], 1);
    __syncthreads();

    // warp 0: find bucket containing rank np-1 (smallest B with cum >= np)
    if (tid < 32 && np > 0) {
        const int CH = NBUCK / 32;          // 256 buckets per lane
        int sum = 0;
        for (int j = 0; j < CH; j++) sum += s_hist[tid * CH + j];
        // exclusive scan across lanes
        int excl = sum;
        #pragma unroll
        for (int off = 1; off < 32; off <<= 1) {
            int v = __shfl_up_sync(0xffffffffu, excl, off);
            if ((int)tid >= off) excl += v;
        }
        excl -= sum;                         // exclusive prefix
        bool has = (excl < np) && (excl + sum >= np);
        unsigned bal = __ballot_sync(0xffffffffu, has);
        int src = __ffs(bal) - 1;
        if ((int)tid == src) {
            int run = excl;
            for (int j = 0; j < CH; j++) {
                run += s_hist[tid * CH + j];
                if (run >= np) { s_bstar = tid * CH + j; break; }
            }
        }
    }
    __syncthreads();

    const int bstar = s_bstar;
    for (int i = tid; i < K; i += 1024) {
        uint64_t k = g_kept[i];
        if ((int)(k >> 39) <= bstar) {
            int p = atomicAdd(&s_pcnt, 1);
            if (p < POOL_CAP) s_pool[p] = k;
        }
    }
    __syncthreads();

    int P = s_pcnt; if (P > POOL_CAP) P = POOL_CAP;
    // exact rank sort of the (small) pool; full key => exact reference order
    for (int i = tid; i < P; i += 1024) {
        uint64_t my = s_pool[i];
        int rk = 0;
        for (int j = 0; j < P; j++) rk += (s_pool[j] < my) ? 1 : 0;
        if (rk < np) s_ord[rk] = (int)((my >> 7) & 0x1FFFu);
    }
    __syncthreads();

    if (tid < MAXDET) {
        float* d = out + (long)OUT_ELEMS + tid * 7;
        if (tid < np) {
            int orig = s_ord[tid];
            float4 c4 = g_corners[orig];
            d[0] = c4.y * 416.0f;
            d[1] = c4.x * 416.0f;
            d[2] = c4.w * 416.0f;
            d[3] = c4.z * 416.0f;
            d[4] = g_conf[orig];
            d[5] = g_clsconf[orig];
            d[6] = g_clspred[orig];
        } else {
            #pragma unroll
            for (int e = 0; e < 7; e++) d[e] = 0.0f;
        }
    }

    if (tid == 0) g_kcount = 0;   // reset for next graph replay
}

extern "C" void kernel_launch(void* const* d_in, const int* in_sizes, int n_in,
                              void* d_out, int out_size)
{
    const float* in      = (const float*)d_in[0];
    const float* anchors = (const float*)d_in[1];
    float* out = (float*)d_out;

    decode_kernel<<<NPRED_TOTAL / 64, 256>>>(in, anchors, out);
    class_nms_kernel<<<NCLS, 256>>>();
    merge_kernel<<<1, 1024>>>(out);
}

// round 9
// speedup vs baseline: 5.4503x; 1.0053x over previous
#include <cuda_runtime.h>
#include <math.h>
#include <stdint.h>

#define NPRED_TOTAL 259584      // 32 * 8112
#define NP0         8112        // predictions in batch 0 (3*52*52)
#define HW_         2704        // 52*52
#define ATTRS       85
#define OUT_ELEMS   22064640    // 32*8112*85
#define MAXDET      100
#define NCLS        80
#define CLS_CAP     1024        // per-class cand cap (expected ~46)
#define KEPT_MAX    8192        // >= NCLS * MAXDET
#define NBUCK       8192        // top-13 bits of 52-bit key (score field)
#define POOL_CAP    1536

// ---- device scratch ----
__device__ float4   g_obox[NP0];
__device__ float4   g_corners[NP0];
__device__ float    g_conf[NP0];
__device__ float    g_clsconf[NP0];
__device__ float    g_clspred[NP0];
__device__ uint64_t g_cls_list[NCLS * CLS_CAP];  // per-class candidate keys
__device__ int      g_cls_cnt[NCLS];             // zero-init; reset per class block
__device__ uint64_t g_kept[KEPT_MAX];            // kept keys (all classes)
__device__ int      g_kcount;                    // zero-init; reset by last block
__device__ int      g_done;                      // ticket; reset by last block

// key (52 bits) = score_inv(32) << 20 | idx(13) << 7 | cls(7)
// ascending key == score desc, then flat idx asc (matches jnp.argmax ties)

__device__ __forceinline__ float sigf(float x) { return 1.0f / (1.0f + expf(-x)); }

// ---------------------------------------------------------------------------
// Decode (structure unchanged from R8, 51.6% DRAM SOL; added streaming cache
// hints: input read-once via __ldcs, output write-once via __stcs).
// ---------------------------------------------------------------------------
__global__ __launch_bounds__(256) void decode_kernel(
    const float* __restrict__ in,
    const float* __restrict__ anchors,
    float* __restrict__ out)
{
    __shared__ float sm[64 * ATTRS];
    const int tx = threadIdx.x;
    const int q  = tx >> 6;
    const int lp = tx & 63;
    const int n  = blockIdx.x * 64 + lp;
    const int b  = n / NP0;
    const int r  = n - b * NP0;
    const int a  = r / HW_;
    const int hw = r - a * HW_;
    const int gy = hw / 52;
    const int gx = hw - gy * 52;

    const float* p = in + ((long)(b * 255 + a * 85)) * HW_ + hw;
    float* row = sm + lp * ATTRS;

    float t[22];
    #pragma unroll
    for (int k = 0; k < 22; k++) {
        int e = q + 4 * k;
        if (e < ATTRS) t[k] = __ldcs(p + (long)e * HW_);
    }

    if (q == 0) {
        row[0] = (sigf(t[0]) + (float)gx) / 52.0f;
        row[4] = sigf(t[1]);
        #pragma unroll
        for (int k = 2; k < 22; k++) row[4 * k] = sigf(t[k]);
    } else if (q == 1) {
        row[1] = (sigf(t[0]) + (float)gy) / 52.0f;
        #pragma unroll
        for (int k = 1; k < 21; k++) row[1 + 4 * k] = sigf(t[k]);
    } else if (q == 2) {
        float aw = anchors[(6 + a) * 2 + 0] * 0.125f;
        row[2] = (expf(t[0]) * aw) / 52.0f;
        #pragma unroll
        for (int k = 1; k < 21; k++) row[2 + 4 * k] = sigf(t[k]);
    } else {
        float ah = anchors[(6 + a) * 2 + 1] * 0.125f;
        row[3] = (expf(t[0]) * ah) / 52.0f;
        #pragma unroll
        for (int k = 1; k < 21; k++) row[3 + 4 * k] = sigf(t[k]);
    }
    __syncthreads();

    {
        const float4* sm4 = (const float4*)sm;
        float4* ob4 = (float4*)(out + (long)blockIdx.x * (64 * ATTRS));
        #pragma unroll 6
        for (int i = tx; i < (64 * ATTRS) / 4; i += 256) __stcs(ob4 + i, sm4[i]);
    }

    if (tx < 64 && n < NP0) {
        float conf = row[4];
        float cc = row[5]; int cp = 0;
        #pragma unroll 16
        for (int c = 1; c < NCLS; c++) {
            float v = row[5 + c];
            if (v > cc) { cc = v; cp = c; }   // strict > : lowest idx on ties
        }
        float score = conf * cc;
        if (score >= 0.5f) {
            float bx = row[0], by = row[1], bw = row[2], bh = row[3];
            float hx = bw * 0.5f, hy = bh * 0.5f;
            float x1 = bx - hx, y1 = by - hy, x2 = bx + hx, y2 = by + hy;
            float off = (float)cp * 4096.0f;
            g_corners[n] = make_float4(x1, y1, x2, y2);
            g_obox[n]    = make_float4(x1 + off, y1 + off, x2 + off, y2 + off);
            g_conf[n]    = conf;
            g_clsconf[n] = cc;
            g_clspred[n] = (float)cp;
            uint64_t key = ((uint64_t)(__float_as_uint(score) ^ 0xFFFFFFFFu) << 20)
                         | ((uint64_t)(unsigned)n << 7) | (unsigned)cp;
            int pos = atomicAdd(&g_cls_cnt[cp], 1);
            if (pos < CLS_CAP) g_cls_list[cp * CLS_CAP + pos] = key;
        }
    }
}

// ---------------------------------------------------------------------------
// Fused NMS: 80 blocks x 256 threads.
//  Per-class phase (identical logic to R8 class_nms): filter/sort/sweep/append.
//  Last-to-finish block (ticket + fences) runs the O(K) histogram top-100
//  merge (the R8 merge_kernel) and writes det rows. Saves one launch.
//  Shared memory is a phase-union: class phase 32KB, merge phase 44KB.
// ---------------------------------------------------------------------------
__global__ __launch_bounds__(256) void nms_kernel(float* __restrict__ out)
{
    __shared__ __align__(16) char buf[45056];           // 44KB union
    uint64_t* s_key  = (uint64_t*)buf;                  // [0,8K)
    uint64_t* s_sort = (uint64_t*)(buf + 8192);         // [8K,16K)
    float4*   s_box  = (float4*)(buf + 16384);          // [16K,32K)
    int*      s_hist = (int*)buf;                       // [0,32K)   (merge)
    uint64_t* s_pool = (uint64_t*)(buf + 32768);        // [32K,44K) (merge)

    __shared__ float4 s_k[MAXDET];
    __shared__ float  s_ka[MAXDET];
    __shared__ int    s_kidx[MAXDET];
    __shared__ int    s_ord[MAXDET];
    __shared__ int    s_nk, s_gbase, s_ticket, s_bstar, s_pcnt;

    const int tid = threadIdx.x;
    const int c   = blockIdx.x;
    int nc = g_cls_cnt[c]; if (nc > CLS_CAP) nc = CLS_CAP;

    for (int i = tid; i < nc; i += 256) s_key[i] = g_cls_list[c * CLS_CAP + i];
    __syncthreads();

    // local rank sort: ascending key = score desc, idx asc
    for (int i = tid; i < nc; i += 256) {
        uint64_t my = s_key[i];
        int rk = 0;
        for (int j = 0; j < nc; j++) rk += (s_key[j] < my) ? 1 : 0;
        s_sort[rk] = my;
    }
    __syncthreads();

    for (int i = tid; i < nc; i += 256) {
        int orig = (int)((s_sort[i] >> 7) & 0x1FFFu);
        s_box[i] = g_obox[orig];
    }
    __syncthreads();

    // warp-0 greedy sweep, lane-parallel over kept boxes
    if (tid < 32) {
        const int lane = tid;
        int nk = 0;
        for (int i = 0; i < nc && nk < MAXDET; i++) {
            float4 B = s_box[i];
            float aC = (B.z - B.x) * (B.w - B.y);
            bool sup = false;
            #pragma unroll
            for (int t = 0; t < 4; t++) {
                int idx = lane + (t << 5);
                if (idx < nk) {
                    float4 K = s_k[idx];
                    float ltx = fmaxf(K.x, B.x), lty = fmaxf(K.y, B.y);
                    float rbx = fminf(K.z, B.z), rby = fminf(K.w, B.w);
                    float iw = fmaxf(rbx - ltx, 0.0f), ih = fmaxf(rby - lty, 0.0f);
                    float inter = iw * ih;
                    float den = s_ka[idx] + aC - inter + 1e-9f;  // a1+a2-inter+eps
                    if (inter / den > 0.4f) sup = true;
                }
            }
            if (__ballot_sync(0xffffffffu, sup) == 0u) {
                if (lane == 0) { s_k[nk] = B; s_ka[nk] = aC; s_kidx[nk] = i; }
                nk++;
                __syncwarp();
            }
        }
        if (lane == 0) s_nk = nk;
    }
    __syncthreads();

    const int nk = s_nk;
    if (tid == 0) s_gbase = (nk > 0) ? atomicAdd(&g_kcount, nk) : 0;
    __syncthreads();
    for (int t = tid; t < nk; t += 256) {
        int gp = s_gbase + t;
        if (gp < KEPT_MAX) g_kept[gp] = s_sort[s_kidx[t]];
    }
    if (tid == 0) g_cls_cnt[c] = 0;       // reset for next graph replay

    // publish: every thread fences its own writes, then one ticket per block
    __threadfence();
    __syncthreads();
    if (tid == 0) s_ticket = atomicAdd(&g_done, 1);
    __syncthreads();
    if (s_ticket != NCLS - 1) return;

    // ===== last block: O(K) histogram top-100 merge =====
    __threadfence();                       // acquire all blocks' g_kept writes
    int K = g_kcount; if (K > KEPT_MAX) K = KEPT_MAX;
    const int np = (K < MAXDET) ? K : MAXDET;

    for (int i = tid; i < NBUCK; i += 256) s_hist[i] = 0;
    if (tid == 0) { s_pcnt = 0; s_bstar = -1; }
    __syncthreads();

    for (int i = tid; i < K; i += 256)
        atomicAdd(&s_hist[(int)(g_kept[i] >> 39)], 1);
    __syncthreads();

    if (tid < 32 && np > 0) {
        const int CH = NBUCK / 32;
        int sum = 0;
        for (int j = 0; j < CH; j++) sum += s_hist[tid * CH + j];
        int excl = sum;
        #pragma unroll
        for (int off = 1; off < 32; off <<= 1) {
            int v = __shfl_up_sync(0xffffffffu, excl, off);
            if ((int)tid >= off) excl += v;
        }
        excl -= sum;
        bool has = (excl < np) && (excl + sum >= np);
        unsigned bal = __ballot_sync(0xffffffffu, has);
        int src = __ffs(bal) - 1;
        if ((int)tid == src) {
            int run = excl;
            for (int j = 0; j < CH; j++) {
                run += s_hist[tid * CH + j];
                if (run >= np) { s_bstar = tid * CH + j; break; }
            }
        }
    }
    __syncthreads();

    const int bstar = s_bstar;
    for (int i = tid; i < K; i += 256) {
        uint64_t k = g_kept[i];
        if ((int)(k >> 39) <= bstar) {
            int p = atomicAdd(&s_pcnt, 1);
            if (p < POOL_CAP) s_pool[p] = k;
        }
    }
    __syncthreads();

    int P = s_pcnt; if (P > POOL_CAP) P = POOL_CAP;
    for (int i = tid; i < P; i += 256) {
        uint64_t my = s_pool[i];
        int rk = 0;
        for (int j = 0; j < P; j++) rk += (s_pool[j] < my) ? 1 : 0;
        if (rk < np) s_ord[rk] = (int)((my >> 7) & 0x1FFFu);
    }
    __syncthreads();

    if (tid < MAXDET) {
        float* d = out + (long)OUT_ELEMS + tid * 7;
        if (tid < np) {
            int orig = s_ord[tid];
            float4 c4 = g_corners[orig];
            d[0] = c4.y * 416.0f;
            d[1] = c4.x * 416.0f;
            d[2] = c4.w * 416.0f;
            d[3] = c4.z * 416.0f;
            d[4] = g_conf[orig];
            d[5] = g_clsconf[orig];
            d[6] = g_clspred[orig];
        } else {
            #pragma unroll
            for (int e = 0; e < 7; e++) d[e] = 0.0f;
        }
    }

    if (tid == 0) { g_kcount = 0; g_done = 0; }   // reset for next replay
}

extern "C" void kernel_launch(void* const* d_in, const int* in_sizes, int n_in,
                              void* d_out, int out_size)
{
    const float* in      = (const float*)d_in[0];
    const float* anchors = (const float*)d_in[1];
    float* out = (float*)d_out;

    decode_kernel<<<NPRED_TOTAL / 64, 256>>>(in, anchors, out);
    nms_kernel<<<NCLS, 256>>>(out);
}

// round 10
// speedup vs baseline: 5.9518x; 1.0920x over previous
#include <cuda_runtime.h>
#include <math.h>
#include <stdint.h>

#define NPRED_TOTAL 259584      // 32 * 8112
#define NP0         8112        // predictions in batch 0 (3*52*52)
#define HW_         2704        // 52*52
#define ATTRS       85
#define OUT_ELEMS   22064640    // 32*8112*85
#define MAXDET      100
#define NCLS        80
#define CLS_CAP     1024        // per-class cand cap (expected ~46)
#define MTX_CAP     256         // matrix fast-path cap (5.8x expected)
#define MTX_W       8           // 256/32 words per threat row
#define KEPT_MAX    8192
#define NBUCK       8192        // top-13 bits of 52-bit key (score field)
#define POOL_CAP    1536

// ---- device scratch ----
__device__ float4   g_obox[NP0];
__device__ float4   g_corners[NP0];
__device__ float    g_conf[NP0];
__device__ float    g_clsconf[NP0];
__device__ float    g_clspred[NP0];
__device__ uint64_t g_cls_list[NCLS * CLS_CAP];
__device__ int      g_cls_cnt[NCLS];             // zero-init; reset per class block
__device__ uint64_t g_kept[KEPT_MAX];
__device__ int      g_kcount;                    // zero-init; reset by last block
__device__ int      g_done;                      // ticket; reset by last block

// key (52 bits) = score_inv(32) << 20 | idx(13) << 7 | cls(7)

__device__ __forceinline__ float sigf(float x) { return 1.0f / (1.0f + expf(-x)); }

// ---------------------------------------------------------------------------
// Decode (unchanged from R9)
// ---------------------------------------------------------------------------
__global__ __launch_bounds__(256) void decode_kernel(
    const float* __restrict__ in,
    const float* __restrict__ anchors,
    float* __restrict__ out)
{
    __shared__ float sm[64 * ATTRS];
    const int tx = threadIdx.x;
    const int q  = tx >> 6;
    const int lp = tx & 63;
    const int n  = blockIdx.x * 64 + lp;
    const int b  = n / NP0;
    const int r  = n - b * NP0;
    const int a  = r / HW_;
    const int hw = r - a * HW_;
    const int gy = hw / 52;
    const int gx = hw - gy * 52;

    const float* p = in + ((long)(b * 255 + a * 85)) * HW_ + hw;
    float* row = sm + lp * ATTRS;

    float t[22];
    #pragma unroll
    for (int k = 0; k < 22; k++) {
        int e = q + 4 * k;
        if (e < ATTRS) t[k] = __ldcs(p + (long)e * HW_);
    }

    if (q == 0) {
        row[0] = (sigf(t[0]) + (float)gx) / 52.0f;
        row[4] = sigf(t[1]);
        #pragma unroll
        for (int k = 2; k < 22; k++) row[4 * k] = sigf(t[k]);
    } else if (q == 1) {
        row[1] = (sigf(t[0]) + (float)gy) / 52.0f;
        #pragma unroll
        for (int k = 1; k < 21; k++) row[1 + 4 * k] = sigf(t[k]);
    } else if (q == 2) {
        float aw = anchors[(6 + a) * 2 + 0] * 0.125f;
        row[2] = (expf(t[0]) * aw) / 52.0f;
        #pragma unroll
        for (int k = 1; k < 21; k++) row[2 + 4 * k] = sigf(t[k]);
    } else {
        float ah = anchors[(6 + a) * 2 + 1] * 0.125f;
        row[3] = (expf(t[0]) * ah) / 52.0f;
        #pragma unroll
        for (int k = 1; k < 21; k++) row[3 + 4 * k] = sigf(t[k]);
    }
    __syncthreads();

    {
        const float4* sm4 = (const float4*)sm;
        float4* ob4 = (float4*)(out + (long)blockIdx.x * (64 * ATTRS));
        #pragma unroll 6
        for (int i = tx; i < (64 * ATTRS) / 4; i += 256) __stcs(ob4 + i, sm4[i]);
    }

    if (tx < 64 && n < NP0) {
        float conf = row[4];
        float cc = row[5]; int cp = 0;
        #pragma unroll 16
        for (int c = 1; c < NCLS; c++) {
            float v = row[5 + c];
            if (v > cc) { cc = v; cp = c; }
        }
        float score = conf * cc;
        if (score >= 0.5f) {
            float bx = row[0], by = row[1], bw = row[2], bh = row[3];
            float hx = bw * 0.5f, hy = bh * 0.5f;
            float x1 = bx - hx, y1 = by - hy, x2 = bx + hx, y2 = by + hy;
            float off = (float)cp * 4096.0f;
            g_corners[n] = make_float4(x1, y1, x2, y2);
            g_obox[n]    = make_float4(x1 + off, y1 + off, x2 + off, y2 + off);
            g_conf[n]    = conf;
            g_clsconf[n] = cc;
            g_clspred[n] = (float)cp;
            uint64_t key = ((uint64_t)(__float_as_uint(score) ^ 0xFFFFFFFFu) << 20)
                         | ((uint64_t)(unsigned)n << 7) | (unsigned)cp;
            int pos = atomicAdd(&g_cls_cnt[cp], 1);
            if (pos < CLS_CAP) g_cls_list[cp * CLS_CAP + pos] = key;
        }
    }
}

// ---------------------------------------------------------------------------
// Fused NMS: 80 blocks x 256 threads.
//  Matrix fast path (nc<=256): thread i builds the bitmask of earlier boxes
//  that suppress i (parallel IoU), then one warp does a trivial bitmask
//  greedy scan. Fallback serial sweep for nc>256. Last block (ticket+fence)
//  runs the O(K) histogram top-100 merge.
// ---------------------------------------------------------------------------
__global__ __launch_bounds__(256) void nms_kernel(float* __restrict__ out)
{
    __shared__ __align__(16) char buf[45056];       // 44KB phase union
    uint64_t* s_key  = (uint64_t*)buf;              // [0,8K)
    uint64_t* s_sort = (uint64_t*)(buf + 8192);     // [8K,16K)
    float4*   s_box  = (float4*)(buf + 16384);      // [16K,32K)
    unsigned* s_thr  = (unsigned*)(buf + 32768);    // [32K,40K): 256 x 8 words
    int*      s_hist = (int*)buf;                   // [0,32K)   (merge)
    uint64_t* s_pool = (uint64_t*)(buf + 32768);    // [32K,44K) (merge)

    __shared__ int s_kidx[MAXDET];
    __shared__ int s_ord[MAXDET];
    __shared__ int s_nk, s_gbase, s_ticket, s_bstar, s_pcnt;

    const int tid = threadIdx.x;
    const int c   = blockIdx.x;
    int nc = g_cls_cnt[c]; if (nc > CLS_CAP) nc = CLS_CAP;

    for (int i = tid; i < nc; i += 256) s_key[i] = g_cls_list[c * CLS_CAP + i];
    __syncthreads();

    // local rank sort (ascending key = score desc, idx asc; keys unique)
    for (int i = tid; i < nc; i += 256) {
        uint64_t my = s_key[i];
        int rk = 0;
        for (int j = 0; j < nc; j++) rk += (s_key[j] < my) ? 1 : 0;
        s_sort[rk] = my;
    }
    __syncthreads();

    for (int i = tid; i < nc; i += 256) {
        int orig = (int)((s_sort[i] >> 7) & 0x1FFFu);
        s_box[i] = g_obox[orig];
    }
    __syncthreads();

    if (nc <= MTX_CAP) {
        // ---- matrix fast path ----
        // thread i: bitmask of j<i with IoU(j as picked, i) > 0.4
        if (tid < nc) {
            unsigned w[MTX_W];
            #pragma unroll
            for (int k = 0; k < MTX_W; k++) w[k] = 0u;
            float4 Q = s_box[tid];
            float aI = (Q.z - Q.x) * (Q.w - Q.y);
            for (int j = 0; j < tid; j++) {
                float4 P = s_box[j];
                float aJ = (P.z - P.x) * (P.w - P.y);
                float ltx = fmaxf(P.x, Q.x), lty = fmaxf(P.y, Q.y);
                float rbx = fminf(P.z, Q.z), rby = fminf(P.w, Q.w);
                float iw = fmaxf(rbx - ltx, 0.0f), ih = fmaxf(rby - lty, 0.0f);
                float inter = iw * ih;
                float den = aJ + aI - inter + 1e-9f;   // a1(picked)+a2-inter+eps
                if (inter / den > 0.4f) w[j >> 5] |= 1u << (j & 31);
            }
            #pragma unroll
            for (int k = 0; k < MTX_W; k++) s_thr[tid * MTX_W + k] = w[k];
        }
        __syncthreads();

        // warp 0: bitmask greedy scan (lane l<8 owns kept word l)
        if (tid < 32) {
            unsigned kw = 0u;
            int nk = 0;
            for (int i = 0; i < nc && nk < MAXDET; i++) {
                unsigned tw = (tid < MTX_W) ? (s_thr[i * MTX_W + tid] & kw) : 0u;
                if (__ballot_sync(0xffffffffu, tw != 0u) == 0u) {
                    if (tid == 0) s_kidx[nk] = i;
                    if (tid == (i >> 5)) kw |= 1u << (i & 31);
                    nk++;
                }
            }
            if (tid == 0) s_nk = nk;
        }
    } else {
        // ---- fallback: serial warp sweep (kept-index indirection) ----
        if (tid < 32) {
            const int lane = tid;
            int nk = 0;
            for (int i = 0; i < nc && nk < MAXDET; i++) {
                float4 B = s_box[i];
                float aC = (B.z - B.x) * (B.w - B.y);
                bool sup = false;
                #pragma unroll
                for (int t = 0; t < 4; t++) {
                    int idx = lane + (t << 5);
                    if (idx < nk) {
                        float4 K = s_box[s_kidx[idx]];
                        float aK = (K.z - K.x) * (K.w - K.y);
                        float ltx = fmaxf(K.x, B.x), lty = fmaxf(K.y, B.y);
                        float rbx = fminf(K.z, B.z), rby = fminf(K.w, B.w);
                        float iw = fmaxf(rbx - ltx, 0.0f), ih = fmaxf(rby - lty, 0.0f);
                        float inter = iw * ih;
                        float den = aK + aC - inter + 1e-9f;
                        if (inter / den > 0.4f) sup = true;
                    }
                }
                if (__ballot_sync(0xffffffffu, sup) == 0u) {
                    if (lane == 0) s_kidx[nk] = i;
                    nk++;
                    __syncwarp();
                }
            }
            if (lane == 0) s_nk = nk;
        }
    }
    __syncthreads();

    const int nk = s_nk;
    if (tid == 0) s_gbase = (nk > 0) ? atomicAdd(&g_kcount, nk) : 0;
    __syncthreads();
    for (int t = tid; t < nk; t += 256) {
        int gp = s_gbase + t;
        if (gp < KEPT_MAX) g_kept[gp] = s_sort[s_kidx[t]];
    }
    if (tid == 0) g_cls_cnt[c] = 0;

    __threadfence();
    __syncthreads();
    if (tid == 0) s_ticket = atomicAdd(&g_done, 1);
    __syncthreads();
    if (s_ticket != NCLS - 1) return;

    // ===== last block: O(K) histogram top-100 merge =====
    __threadfence();
    int K = g_kcount; if (K > KEPT_MAX) K = KEPT_MAX;
    const int np = (K < MAXDET) ? K : MAXDET;

    for (int i = tid; i < NBUCK; i += 256) s_hist[i] = 0;
    if (tid == 0) { s_pcnt = 0; s_bstar = -1; }
    __syncthreads();

    for (int i = tid; i < K; i += 256)
        atomicAdd(&s_hist[(int)(g_kept[i] >> 39)], 1);
    __syncthreads();

    if (tid < 32 && np > 0) {
        const int CH = NBUCK / 32;
        int sum = 0;
        for (int j = 0; j < CH; j++) sum += s_hist[tid * CH + j];
        int excl = sum;
        #pragma unroll
        for (int off = 1; off < 32; off <<= 1) {
            int v = __shfl_up_sync(0xffffffffu, excl, off);
            if ((int)tid >= off) excl += v;
        }
        excl -= sum;
        bool has = (excl < np) && (excl + sum >= np);
        unsigned bal = __ballot_sync(0xffffffffu, has);
        int src = __ffs(bal) - 1;
        if ((int)tid == src) {
            int run = excl;
            for (int j = 0; j < CH; j++) {
                run += s_hist[tid * CH + j];
                if (run >= np) { s_bstar = tid * CH + j; break; }
            }
        }
    }
    __syncthreads();

    const int bstar = s_bstar;
    for (int i = tid; i < K; i += 256) {
        uint64_t k = g_kept[i];
        if ((int)(k >> 39) <= bstar) {
            int p = atomicAdd(&s_pcnt, 1);
            if (p < POOL_CAP) s_pool[p] = k;
        }
    }
    __syncthreads();

    int P = s_pcnt; if (P > POOL_CAP) P = POOL_CAP;
    for (int i = tid; i < P; i += 256) {
        uint64_t my = s_pool[i];
        int rk = 0;
        for (int j = 0; j < P; j++) rk += (s_pool[j] < my) ? 1 : 0;
        if (rk < np) s_ord[rk] = (int)((my >> 7) & 0x1FFFu);
    }
    __syncthreads();

    if (tid < MAXDET) {
        float* d = out + (long)OUT_ELEMS + tid * 7;
        if (tid < np) {
            int orig = s_ord[tid];
            float4 c4 = g_corners[orig];
            d[0] = c4.y * 416.0f;
            d[1] = c4.x * 416.0f;
            d[2] = c4.w * 416.0f;
            d[3] = c4.z * 416.0f;
            d[4] = g_conf[orig];
            d[5] = g_clsconf[orig];
            d[6] = g_clspred[orig];
        } else {
            #pragma unroll
            for (int e = 0; e < 7; e++) d[e] = 0.0f;
        }
    }

    if (tid == 0) { g_kcount = 0; g_done = 0; }
}

extern "C" void kernel_launch(void* const* d_in, const int* in_sizes, int n_in,
                              void* d_out, int out_size)
{
    const float* in      = (const float*)d_in[0];
    const float* anchors = (const float*)d_in[1];
    float* out = (float*)d_out;

    decode_kernel<<<NPRED_TOTAL / 64, 256>>>(in, anchors, out);
    nms_kernel<<<NCLS, 256>>>(out);
}

// round 11
// speedup vs baseline: 6.3309x; 1.0637x over previous
#include <cuda_runtime.h>
#include <math.h>
#include <stdint.h>

#define NPRED_TOTAL 259584      // 32 * 8112
#define NP0         8112        // predictions in batch 0 (3*52*52)
#define HW_         2704        // 52*52
#define ATTRS       85
#define OUT_ELEMS   22064640    // 32*8112*85
#define MAXDET      100
#define NCLS        80
#define CLS_CAP     1024
#define MTX_CAP     256
#define MTX_W       8
#define KEPT_MAX    8192
#define NBUCK       8192        // (key>>31)&0x1FFF : exp-LSB + 12 mantissa bits
#define POOL_CAP    1536
#define B0_BLOCKS   127         // blocks covering all of batch 0 (127*64 >= 8112)
#define TOT_BLOCKS  (NPRED_TOTAL / 64)

// ---- device scratch ----
__device__ float4   g_obox[NP0];
__device__ float4   g_corners[NP0];
__device__ float    g_conf[NP0];
__device__ float    g_clsconf[NP0];
__device__ float    g_clspred[NP0];
__device__ uint64_t g_cls_list[NCLS * CLS_CAP];
__device__ int      g_cls_cnt[NCLS];
__device__ uint64_t g_kept[KEPT_MAX];
__device__ int      g_kcount;
__device__ int      g_done;

// key (52 bits) = score_inv(32) << 20 | idx(13) << 7 | cls(7)

__device__ __forceinline__ float sigf(float x) { return 1.0f / (1.0f + expf(-x)); }

// ---------------------------------------------------------------------------
// Decode (R10 body, with a block offset so it can be launched in two ranges)
// ---------------------------------------------------------------------------
__global__ __launch_bounds__(256) void decode_kernel(
    const float* __restrict__ in,
    const float* __restrict__ anchors,
    float* __restrict__ out,
    int blk0)
{
    __shared__ float sm[64 * ATTRS];
    const int blk = blockIdx.x + blk0;
    const int tx = threadIdx.x;
    const int q  = tx >> 6;
    const int lp = tx & 63;
    const int n  = blk * 64 + lp;
    const int b  = n / NP0;
    const int r  = n - b * NP0;
    const int a  = r / HW_;
    const int hw = r - a * HW_;
    const int gy = hw / 52;
    const int gx = hw - gy * 52;

    const float* p = in + ((long)(b * 255 + a * 85)) * HW_ + hw;
    float* row = sm + lp * ATTRS;

    float t[22];
    #pragma unroll
    for (int k = 0; k < 22; k++) {
        int e = q + 4 * k;
        if (e < ATTRS) t[k] = __ldcs(p + (long)e * HW_);
    }

    if (q == 0) {
        row[0] = (sigf(t[0]) + (float)gx) / 52.0f;
        row[4] = sigf(t[1]);
        #pragma unroll
        for (int k = 2; k < 22; k++) row[4 * k] = sigf(t[k]);
    } else if (q == 1) {
        row[1] = (sigf(t[0]) + (float)gy) / 52.0f;
        #pragma unroll
        for (int k = 1; k < 21; k++) row[1 + 4 * k] = sigf(t[k]);
    } else if (q == 2) {
        float aw = anchors[(6 + a) * 2 + 0] * 0.125f;
        row[2] = (expf(t[0]) * aw) / 52.0f;
        #pragma unroll
        for (int k = 1; k < 21; k++) row[2 + 4 * k] = sigf(t[k]);
    } else {
        float ah = anchors[(6 + a) * 2 + 1] * 0.125f;
        row[3] = (expf(t[0]) * ah) / 52.0f;
        #pragma unroll
        for (int k = 1; k < 21; k++) row[3 + 4 * k] = sigf(t[k]);
    }
    __syncthreads();

    {
        const float4* sm4 = (const float4*)sm;
        float4* ob4 = (float4*)(out + (long)blk * (64 * ATTRS));
        #pragma unroll 6
        for (int i = tx; i < (64 * ATTRS) / 4; i += 256) __stcs(ob4 + i, sm4[i]);
    }

    if (tx < 64 && n < NP0) {
        float conf = row[4];
        float cc = row[5]; int cp = 0;
        #pragma unroll 16
        for (int c = 1; c < NCLS; c++) {
            float v = row[5 + c];
            if (v > cc) { cc = v; cp = c; }
        }
        float score = conf * cc;
        if (score >= 0.5f) {
            float bx = row[0], by = row[1], bw = row[2], bh = row[3];
            float hx = bw * 0.5f, hy = bh * 0.5f;
            float x1 = bx - hx, y1 = by - hy, x2 = bx + hx, y2 = by + hy;
            float off = (float)cp * 4096.0f;
            g_corners[n] = make_float4(x1, y1, x2, y2);
            g_obox[n]    = make_float4(x1 + off, y1 + off, x2 + off, y2 + off);
            g_conf[n]    = conf;
            g_clsconf[n] = cc;
            g_clspred[n] = (float)cp;
            uint64_t key = ((uint64_t)(__float_as_uint(score) ^ 0xFFFFFFFFu) << 20)
                         | ((uint64_t)(unsigned)n << 7) | (unsigned)cp;
            int pos = atomicAdd(&g_cls_cnt[cp], 1);
            if (pos < CLS_CAP) g_cls_list[cp * CLS_CAP + pos] = key;
        }
    }
}

// ---------------------------------------------------------------------------
// Fused NMS (R10 structure; merge buckets refined to exp-LSB+mantissa bits)
// ---------------------------------------------------------------------------
__global__ __launch_bounds__(256) void nms_kernel(float* __restrict__ out)
{
    __shared__ __align__(16) char buf[45056];
    uint64_t* s_key  = (uint64_t*)buf;
    uint64_t* s_sort = (uint64_t*)(buf + 8192);
    float4*   s_box  = (float4*)(buf + 16384);
    unsigned* s_thr  = (unsigned*)(buf + 32768);
    int*      s_hist = (int*)buf;
    uint64_t* s_pool = (uint64_t*)(buf + 32768);

    __shared__ int s_kidx[MAXDET];
    __shared__ int s_ord[MAXDET];
    __shared__ int s_nk, s_gbase, s_ticket, s_bstar, s_pcnt;

    const int tid = threadIdx.x;
    const int c   = blockIdx.x;
    int nc = g_cls_cnt[c]; if (nc > CLS_CAP) nc = CLS_CAP;

    for (int i = tid; i < nc; i += 256) s_key[i] = g_cls_list[c * CLS_CAP + i];
    __syncthreads();

    for (int i = tid; i < nc; i += 256) {
        uint64_t my = s_key[i];
        int rk = 0;
        for (int j = 0; j < nc; j++) rk += (s_key[j] < my) ? 1 : 0;
        s_sort[rk] = my;
    }
    __syncthreads();

    for (int i = tid; i < nc; i += 256) {
        int orig = (int)((s_sort[i] >> 7) & 0x1FFFu);
        s_box[i] = g_obox[orig];
    }
    __syncthreads();

    if (nc <= MTX_CAP) {
        if (tid < nc) {
            unsigned w[MTX_W];
            #pragma unroll
            for (int k = 0; k < MTX_W; k++) w[k] = 0u;
            float4 Q = s_box[tid];
            float aI = (Q.z - Q.x) * (Q.w - Q.y);
            for (int j = 0; j < tid; j++) {
                float4 P = s_box[j];
                float aJ = (P.z - P.x) * (P.w - P.y);
                float ltx = fmaxf(P.x, Q.x), lty = fmaxf(P.y, Q.y);
                float rbx = fminf(P.z, Q.z), rby = fminf(P.w, Q.w);
                float iw = fmaxf(rbx - ltx, 0.0f), ih = fmaxf(rby - lty, 0.0f);
                float inter = iw * ih;
                float den = aJ + aI - inter + 1e-9f;
                if (inter / den > 0.4f) w[j >> 5] |= 1u << (j & 31);
            }
            #pragma unroll
            for (int k = 0; k < MTX_W; k++) s_thr[tid * MTX_W + k] = w[k];
        }
        __syncthreads();

        if (tid < 32) {
            unsigned kw = 0u;
            int nk = 0;
            for (int i = 0; i < nc && nk < MAXDET; i++) {
                unsigned tw = (tid < MTX_W) ? (s_thr[i * MTX_W + tid] & kw) : 0u;
                if (__ballot_sync(0xffffffffu, tw != 0u) == 0u) {
                    if (tid == 0) s_kidx[nk] = i;
                    if (tid == (i >> 5)) kw |= 1u << (i & 31);
                    nk++;
                }
            }
            if (tid == 0) s_nk = nk;
        }
    } else {
        if (tid < 32) {
            const int lane = tid;
            int nk = 0;
            for (int i = 0; i < nc && nk < MAXDET; i++) {
                float4 B = s_box[i];
                float aC = (B.z - B.x) * (B.w - B.y);
                bool sup = false;
                #pragma unroll
                for (int t = 0; t < 4; t++) {
                    int idx = lane + (t << 5);
                    if (idx < nk) {
                        float4 K = s_box[s_kidx[idx]];
                        float aK = (K.z - K.x) * (K.w - K.y);
                        float ltx = fmaxf(K.x, B.x), lty = fmaxf(K.y, B.y);
                        float rbx = fminf(K.z, B.z), rby = fminf(K.w, B.w);
                        float iw = fmaxf(rbx - ltx, 0.0f), ih = fmaxf(rby - lty, 0.0f);
                        float inter = iw * ih;
                        float den = aK + aC - inter + 1e-9f;
                        if (inter / den > 0.4f) sup = true;
                    }
                }
                if (__ballot_sync(0xffffffffu, sup) == 0u) {
                    if (lane == 0) s_kidx[nk] = i;
                    nk++;
                    __syncwarp();
                }
            }
            if (lane == 0) s_nk = nk;
        }
    }
    __syncthreads();

    const int nk = s_nk;
    if (tid == 0) s_gbase = (nk > 0) ? atomicAdd(&g_kcount, nk) : 0;
    __syncthreads();
    for (int t = tid; t < nk; t += 256) {
        int gp = s_gbase + t;
        if (gp < KEPT_MAX) g_kept[gp] = s_sort[s_kidx[t]];
    }
    if (tid == 0) g_cls_cnt[c] = 0;

    __threadfence();
    __syncthreads();
    if (tid == 0) s_ticket = atomicAdd(&g_done, 1);
    __syncthreads();
    if (s_ticket != NCLS - 1) return;

    // ===== last block: histogram top-100 merge (fine buckets) =====
    __threadfence();
    int K = g_kcount; if (K > KEPT_MAX) K = KEPT_MAX;
    const int np = (K < MAXDET) ? K : MAXDET;

    for (int i = tid; i < NBUCK; i += 256) s_hist[i] = 0;
    if (tid == 0) { s_pcnt = 0; s_bstar = -1; }
    __syncthreads();

    for (int i = tid; i < K; i += 256)
        atomicAdd(&s_hist[(int)((g_kept[i] >> 31) & 0x1FFFu)], 1);
    __syncthreads();

    if (tid < 32 && np > 0) {
        const int CH = NBUCK / 32;
        int sum = 0;
        for (int j = 0; j < CH; j++) sum += s_hist[tid * CH + j];
        int excl = sum;
        #pragma unroll
        for (int off = 1; off < 32; off <<= 1) {
            int v = __shfl_up_sync(0xffffffffu, excl, off);
            if ((int)tid >= off) excl += v;
        }
        excl -= sum;
        bool has = (excl < np) && (excl + sum >= np);
        unsigned bal = __ballot_sync(0xffffffffu, has);
        int src = __ffs(bal) - 1;
        if ((int)tid == src) {
            int run = excl;
            for (int j = 0; j < CH; j++) {
                run += s_hist[tid * CH + j];
                if (run >= np) { s_bstar = tid * CH + j; break; }
            }
        }
    }
    __syncthreads();

    const int bstar = s_bstar;
    for (int i = tid; i < K; i += 256) {
        uint64_t k = g_kept[i];
        if ((int)((k >> 31) & 0x1FFFu) <= bstar) {
            int p = atomicAdd(&s_pcnt, 1);
            if (p < POOL_CAP) s_pool[p] = k;
        }
    }
    __syncthreads();

    int P = s_pcnt; if (P > POOL_CAP) P = POOL_CAP;
    for (int i = tid; i < P; i += 256) {
        uint64_t my = s_pool[i];
        int rk = 0;
        for (int j = 0; j < P; j++) rk += (s_pool[j] < my) ? 1 : 0;
        if (rk < np) s_ord[rk] = (int)((my >> 7) & 0x1FFFu);
    }
    __syncthreads();

    if (tid < MAXDET) {
        float* d = out + (long)OUT_ELEMS + tid * 7;
        if (tid < np) {
            int orig = s_ord[tid];
            float4 c4 = g_corners[orig];
            d[0] = c4.y * 416.0f;
            d[1] = c4.x * 416.0f;
            d[2] = c4.w * 416.0f;
            d[3] = c4.z * 416.0f;
            d[4] = g_conf[orig];
            d[5] = g_clsconf[orig];
            d[6] = g_clspred[orig];
        } else {
            #pragma unroll
            for (int e = 0; e < 7; e++) d[e] = 0.0f;
        }
    }

    if (tid == 0) { g_kcount = 0; g_done = 0; }
}

// ---------------------------------------------------------------------------
// Launch: fork/join. Batch-0 decode first, then NMS (side stream, event-
// ordered) overlaps the remaining 31/32 of decode on the main stream.
// ---------------------------------------------------------------------------
extern "C" void kernel_launch(void* const* d_in, const int* in_sizes, int n_in,
                              void* d_out, int out_size)
{
    const float* in      = (const float*)d_in[0];
    const float* anchors = (const float*)d_in[1];
    float* out = (float*)d_out;

    static cudaStream_t s2 = nullptr;
    static cudaEvent_t  e1 = nullptr, e2 = nullptr;
    if (!s2) {   // first call = uncaptured correctness run; reused afterwards
        cudaStreamCreateWithFlags(&s2, cudaStreamNonBlocking);
        cudaEventCreateWithFlags(&e1, cudaEventDisableTiming);
        cudaEventCreateWithFlags(&e2, cudaEventDisableTiming);
    }

    // batch-0 decode on the main (capture-origin) stream
    decode_kernel<<<B0_BLOCKS, 256>>>(in, anchors, out, 0);
    cudaEventRecord(e1, 0);

    // fork: NMS on side stream, ordered after batch-0 decode
    cudaStreamWaitEvent(s2, e1, 0);
    nms_kernel<<<NCLS, 256, 0, s2>>>(out);

    // remaining decode overlaps NMS on the main stream
    decode_kernel<<<TOT_BLOCKS - B0_BLOCKS, 256>>>(in, anchors, out, B0_BLOCKS);

    // join: main stream waits for NMS before capture ends
    cudaEventRecord(e2, s2);
    cudaStreamWaitEvent(0, e2, 0);
}